// round 15
// baseline (speedup 1.0000x reference)
#include <cuda_runtime.h>
#include <cstdint>
#include <math.h>

// Problem constants
//   x: (1,128,32,32,32) fp32 ; w_qkv: (384,128) fp32
//   subsample ::2 -> N = 4096 tokens, HEADS=4, head_dim=32, d_half=16
//   scale=1/sqrt(32), LAMBDA=0.1
//   out flat index = h*131072 + n*32 + d  (validated R4/R5)

#define N_TOK    4096
#define LAMBDA_F 0.1f
#define NSPLIT   2
#define KEYS_PER_SPLIT (N_TOK / NSPLIT)
#define TILES_PER_SPLIT (KEYS_PER_SPLIT / 32)
// scale * log2(e): scores computed in log2 domain for raw ex2
#define QSCALE_LOG2E 0.2550347222435f

// Scratch (device globals — no allocation)
__device__ float g_qkv[384 * 4096];        // q,k rows: [o][n], o = h*96 + r
__device__ float g_vT[4 * 4096 * 32];      // v: [h][n][d]
// split-K partials: o [split][h][row][state][d], l [split][h][row][state]
__device__ float g_po[NSPLIT * 4 * 4096 * 2 * 32];
__device__ float g_pl[NSPLIT * 4 * 4096 * 2];

// ---------------------------------------------------------------------------
__device__ __forceinline__ uint32_t f2tf32(float x) {
    uint32_t t;
    asm("cvt.rna.tf32.f32 %0, %1;" : "=r"(t) : "f"(x));
    return t;
}
__device__ __forceinline__ float ex2f(float x) {
    float y;
    asm("ex2.approx.ftz.f32 %0, %1;" : "=f"(y) : "f"(x));
    return y;
}
// pack {lo, hi} -> f16x2
__device__ __forceinline__ uint32_t pack_f16x2(float lo, float hi) {
    uint32_t r;
    asm("cvt.rn.f16x2.f32 %0, %1, %2;" : "=r"(r) : "f"(hi), "f"(lo));
    return r;
}
// D += A * B  (m16n8k8, tf32 in, fp32 accum)
__device__ __forceinline__ void mma_tf32(float* d, const uint32_t* a, const uint32_t* b) {
    asm volatile(
        "mma.sync.aligned.m16n8k8.row.col.f32.tf32.tf32.f32 "
        "{%0,%1,%2,%3}, {%4,%5,%6,%7}, {%8,%9}, {%0,%1,%2,%3};"
        : "+f"(d[0]), "+f"(d[1]), "+f"(d[2]), "+f"(d[3])
        : "r"(a[0]), "r"(a[1]), "r"(a[2]), "r"(a[3]), "r"(b[0]), "r"(b[1]));
}
// D += A * B  (m16n8k16, f16 in, fp32 accum)
__device__ __forceinline__ void mma_f16(float* d, const uint32_t* a, const uint32_t* b) {
    asm volatile(
        "mma.sync.aligned.m16n8k16.row.col.f32.f16.f16.f32 "
        "{%0,%1,%2,%3}, {%4,%5,%6,%7}, {%8,%9}, {%0,%1,%2,%3};"
        : "+f"(d[0]), "+f"(d[1]), "+f"(d[2]), "+f"(d[3])
        : "r"(a[0]), "r"(a[1]), "r"(a[2]), "r"(a[3]), "r"(b[0]), "r"(b[1]));
}

// ===========================================================================
// Kernel 1: QKV projection, restructured for latency hiding.
// tile 64o x 32n, grid (128 n-tiles, 6 o-tiles) = 768 CTAs, 256 threads.
// ===========================================================================
__global__ __launch_bounds__(256) void qkv_proj_kernel(const float* __restrict__ x,
                                                       const float* __restrict__ w) {
    __shared__ float sW[64 * 68];   // [o_local][k_local], pad 68
    __shared__ float sX[64 * 36];   // [c_local][n_local], pad 36
    const int tid = threadIdx.x;
    const int n0 = blockIdx.x * 32;
    const int o0 = blockIdx.y * 64;
    const int tx = tid & 7;         // n group (4 cols)
    const int ty = tid >> 3;        // o group (2 rows), 0..31

    float acc[2][4] = {};

    for (int k0 = 0; k0 < 128; k0 += 64) {
        __syncthreads();
        // W tile: 64 rows x 16 float4
        for (int i = tid; i < 64 * 16; i += 256) {
            int r = i >> 4, q4 = i & 15;
            *(float4*)&sW[r * 68 + q4 * 4] =
                *(const float4*)&w[(o0 + r) * 128 + k0 + q4 * 4];
        }
        // X tile: strided gather, 64 ch x 32 n
        for (int i = tid; i < 64 * 32; i += 256) {
            int cl = i >> 5, j = i & 31;
            int n = n0 + j;
            int hh = n >> 8, ww = (n >> 4) & 15, zz = n & 15;
            sX[cl * 36 + j] = x[(k0 + cl) * 32768 + hh * 2048 + ww * 64 + zz * 2];
        }
        __syncthreads();

        #pragma unroll
        for (int k = 0; k < 64; k += 4) {
            float xk[4][4];
            #pragma unroll
            for (int kk = 0; kk < 4; kk++) {
                float4 xv = *(float4*)&sX[(k + kk) * 36 + 4 * tx];
                xk[kk][0] = xv.x; xk[kk][1] = xv.y; xk[kk][2] = xv.z; xk[kk][3] = xv.w;
            }
            #pragma unroll
            for (int i = 0; i < 2; i++) {
                float4 wv = *(float4*)&sW[(2 * ty + i) * 68 + k];
                float wk[4] = {wv.x, wv.y, wv.z, wv.w};
                #pragma unroll
                for (int kk = 0; kk < 4; kk++)
                    #pragma unroll
                    for (int j = 0; j < 4; j++)
                        acc[i][j] += wk[kk] * xk[kk][j];
            }
        }
    }

    #pragma unroll
    for (int i = 0; i < 2; i++) {
        int o = o0 + 2 * ty + i;
        int r = o % 96;
        if (r < 64) {
            *(float4*)&g_qkv[o * 4096 + n0 + 4 * tx] =
                make_float4(acc[i][0], acc[i][1], acc[i][2], acc[i][3]);
        } else {
            int h = o / 96, d = r - 64;
            int nb = n0 + 4 * tx;
            #pragma unroll
            for (int j = 0; j < 4; j++)
                g_vT[(h * 4096 + nb + j) * 32 + d] = acc[i][j];
        }
    }
}

// ===========================================================================
// Kernel 2: dual-softmax attention, tf32 QK + register P + f16 PV.
// grid (64 row-tiles, 4 heads, 2 splits) = 512 CTAs, 128 threads (4 warps).
// Double-buffered smem, ONE __syncthreads per 32-key tile.
// ===========================================================================
__global__ __launch_bounds__(128, 4) void diff_attn_mma(void) {
    __shared__ __align__(16) uint32_t sK [2][32 * 40];  // K fp32 [dim][key], pad 40
    __shared__ __align__(16) uint32_t sVh[2][16 * 40];  // V f16x2 [keypair][dim], pad 40

    const int tid  = threadIdx.x;
    const int lane = tid & 31;
    const int warp = tid >> 5;
    const int h    = blockIdx.y;
    const int i0   = blockIdx.x * 64;
    const int spl  = blockIdx.z;
    const int kbase = spl * KEYS_PER_SPLIT;

    const float* qb = g_qkv + (h * 96) * 4096;
    const float* kb = qb + 32 * 4096;
    const float* vb = g_vT + h * 4096 * 32;

    const int qr = lane >> 2;   // 0..7
    const int qc = lane & 3;    // 0..3

    // ---- persistent Q fragments (rna->tf32, scale*log2e folded) ----
    uint32_t qf[2][2][4];
    {
        const int r = i0 + warp * 16 + qr;
        #pragma unroll
        for (int hf = 0; hf < 2; hf++)
            #pragma unroll
            for (int kc = 0; kc < 2; kc++) {
                int d = hf * 16 + kc * 8 + qc;
                qf[hf][kc][0] = f2tf32(qb[d * 4096 + r] * QSCALE_LOG2E);
                qf[hf][kc][1] = f2tf32(qb[d * 4096 + r + 8] * QSCALE_LOG2E);
                qf[hf][kc][2] = f2tf32(qb[(d + 4) * 4096 + r] * QSCALE_LOG2E);
                qf[hf][kc][3] = f2tf32(qb[(d + 4) * 4096 + r + 8] * QSCALE_LOG2E);
            }
    }

    float of[2][4][4] = {};    // [state][nc(dim 8-chunk)][frag]
    float lacc[2][2] = {};     // [state][lo/hi row]

    // fill mapping: K rows pd,pd+16 x 4 keys ; V keypair pd x 4 dims
    const int pd = tid >> 3;          // 0..15
    const int pc = (tid & 7) * 4;     // 0..28

    float4 kfA, kfB, vfA, vfB;
    // prologue: tile 0 -> regs -> stage 0 ; tile 1 -> regs
    kfA = *(const float4*)&kb[pd * 4096 + kbase + pc];
    kfB = *(const float4*)&kb[(pd + 16) * 4096 + kbase + pc];
    vfA = *(const float4*)&vb[(kbase + 2 * pd) * 32 + pc];
    vfB = *(const float4*)&vb[(kbase + 2 * pd + 1) * 32 + pc];
    {
        *(float4*)&sK[0][pd * 40 + pc]        = kfA;
        *(float4*)&sK[0][(pd + 16) * 40 + pc] = kfB;
        uint4 vp;
        vp.x = pack_f16x2(vfA.x, vfB.x);
        vp.y = pack_f16x2(vfA.y, vfB.y);
        vp.z = pack_f16x2(vfA.z, vfB.z);
        vp.w = pack_f16x2(vfA.w, vfB.w);
        *(uint4*)&sVh[0][pd * 40 + pc] = vp;
    }
    {
        const int j0 = kbase + 32;
        kfA = *(const float4*)&kb[pd * 4096 + j0 + pc];
        kfB = *(const float4*)&kb[(pd + 16) * 4096 + j0 + pc];
        vfA = *(const float4*)&vb[(j0 + 2 * pd) * 32 + pc];
        vfB = *(const float4*)&vb[(j0 + 2 * pd + 1) * 32 + pc];
    }
    __syncthreads();

    for (int jt = 0; jt < TILES_PER_SPLIT; jt++) {
        const int cur = jt & 1;
        const int nxt = cur ^ 1;

        // store tile jt+1 (in regs) into the other stage; prefetch jt+2
        if (jt + 1 < TILES_PER_SPLIT) {
            *(float4*)&sK[nxt][pd * 40 + pc]        = kfA;
            *(float4*)&sK[nxt][(pd + 16) * 40 + pc] = kfB;
            uint4 vp;
            vp.x = pack_f16x2(vfA.x, vfB.x);
            vp.y = pack_f16x2(vfA.y, vfB.y);
            vp.z = pack_f16x2(vfA.z, vfB.z);
            vp.w = pack_f16x2(vfA.w, vfB.w);
            *(uint4*)&sVh[nxt][pd * 40 + pc] = vp;
        }
        if (jt + 2 < TILES_PER_SPLIT) {
            const int j0 = kbase + (jt + 2) * 32;
            kfA = *(const float4*)&kb[pd * 4096 + j0 + pc];
            kfB = *(const float4*)&kb[(pd + 16) * 4096 + j0 + pc];
            vfA = *(const float4*)&vb[(j0 + 2 * pd) * 32 + pc];
            vfB = *(const float4*)&vb[(j0 + 2 * pd + 1) * 32 + pc];
        }

        // ---- MMA1 (tf32) + exp + in-register f16 A-frag pack, both states ----
        const uint32_t* cK = sK[cur];
        const uint32_t* cV = sVh[cur];
        uint32_t pa[2][2][4];   // [state][k16-chunk][a-frag]
        #pragma unroll
        for (int hf = 0; hf < 2; hf++) {
            float sf[4][4] = {};
            #pragma unroll
            for (int kc = 0; kc < 2; kc++) {
                const int drow = hf * 16 + kc * 8 + qc;
                #pragma unroll
                for (int nc = 0; nc < 4; nc++) {
                    uint32_t b[2];
                    b[0] = cK[drow * 40 + nc * 8 + qr];
                    b[1] = cK[(drow + 4) * 40 + nc * 8 + qr];
                    mma_tf32(sf[nc], qf[hf][kc], b);
                }
            }
            float ll = 0.f, lh = 0.f;
            #pragma unroll
            for (int nc = 0; nc < 4; nc++) {
                float e0 = ex2f(sf[nc][0]);
                float e1 = ex2f(sf[nc][1]);
                float e2 = ex2f(sf[nc][2]);
                float e3 = ex2f(sf[nc][3]);
                ll += e0 + e1;
                lh += e2 + e3;
                const int ch = nc >> 1;
                const int aoff = (nc & 1) * 2;
                pa[hf][ch][aoff + 0] = pack_f16x2(e0, e1);
                pa[hf][ch][aoff + 1] = pack_f16x2(e2, e3);
            }
            lacc[hf][0] += ll;
            lacc[hf][1] += lh;
        }

        // ---- PV (f16 m16n8k16): O_s += P_s x V, V fragments shared ----
        #pragma unroll
        for (int c = 0; c < 2; c++) {
            #pragma unroll
            for (int nc = 0; nc < 4; nc++) {
                uint32_t b[2];
                b[0] = cV[(c * 8 + qc) * 40 + nc * 8 + qr];
                b[1] = cV[(c * 8 + qc + 4) * 40 + nc * 8 + qr];
                mma_f16(of[0][nc], pa[0][c], b);
                mma_f16(of[1][nc], pa[1][c], b);
            }
        }

        __syncthreads();   // single barrier: separates stage reuse across iters
    }

    // ---- epilogue: quad-reduce l, write RAW partials ----
    #pragma unroll
    for (int s = 1; s < 4; s <<= 1) {
        #pragma unroll
        for (int hf = 0; hf < 2; hf++) {
            lacc[hf][0] += __shfl_xor_sync(0xffffffffu, lacc[hf][0], s);
            lacc[hf][1] += __shfl_xor_sync(0xffffffffu, lacc[hf][1], s);
        }
    }

    const int row_lo = i0 + warp * 16 + qr;
    const int b_lo = ((spl * 4 + h) * 4096 + row_lo) * 2;
    const int b_hi = b_lo + 16;   // row_lo + 8
    #pragma unroll
    for (int st = 0; st < 2; st++) {
        #pragma unroll
        for (int nc = 0; nc < 4; nc++) {
            const int col = nc * 8 + qc * 2;
            *(float2*)&g_po[(b_lo + st) * 32 + col] =
                make_float2(of[st][nc][0], of[st][nc][1]);
            *(float2*)&g_po[(b_hi + st) * 32 + col] =
                make_float2(of[st][nc][2], of[st][nc][3]);
        }
    }
    if (qc == 0) {
        #pragma unroll
        for (int st = 0; st < 2; st++) {
            g_pl[b_lo + st] = lacc[st][0];
            g_pl[b_hi + st] = lacc[st][1];
        }
    }
}

// ===========================================================================
// Kernel 3: split-K reduce + differential combine.
// ===========================================================================
__global__ __launch_bounds__(256) void diff_reduce(float* __restrict__ out) {
    const int idx = blockIdx.x * 256 + threadIdx.x;   // over 4*4096*32
    const int d   = idx & 31;
    const int hn  = idx >> 5;                          // h*4096 + n

    const int STRIDE_O = 4 * 4096 * 2 * 32;
    const int STRIDE_L = 4 * 4096 * 2;
    const int bo = hn * 2 * 32;
    const int bl = hn * 2;

    float o1 = g_po[bo + d]      + g_po[STRIDE_O + bo + d];
    float o2 = g_po[bo + 32 + d] + g_po[STRIDE_O + bo + 32 + d];
    float l1 = g_pl[bl]          + g_pl[STRIDE_L + bl];
    float l2 = g_pl[bl + 1]      + g_pl[STRIDE_L + bl + 1];

    out[idx] = o1 / l1 - LAMBDA_F * (o2 / l2);
}

// ===========================================================================
extern "C" void kernel_launch(void* const* d_in, const int* in_sizes, int n_in,
                              void* d_out, int out_size) {
    const float* x = (const float*)d_in[0];       // (1,128,32,32,32)
    const float* w = (const float*)d_in[1];       // (384,128)
    float* out = (float*)d_out;                   // (1,128,16,16,16) fp32

    qkv_proj_kernel<<<dim3(128, 6), 256>>>(x, w);
    diff_attn_mma<<<dim3(64, 4, NSPLIT), 128>>>();
    diff_reduce<<<(4 * 4096 * 32) / 256, 256>>>(out);
}

// round 16
// speedup vs baseline: 1.2375x; 1.2375x over previous
#include <cuda_runtime.h>
#include <cstdint>
#include <math.h>

// Problem constants
//   x: (1,128,32,32,32) fp32 ; w_qkv: (384,128) fp32
//   subsample ::2 -> N = 4096 tokens, HEADS=4, head_dim=32, d_half=16
//   scale=1/sqrt(32), LAMBDA=0.1
//   out flat index = h*131072 + n*32 + d  (validated R4/R5)

#define N_TOK    4096
#define LAMBDA_F 0.1f
#define NSPLIT   2
#define KEYS_PER_SPLIT (N_TOK / NSPLIT)
#define TILES_PER_SPLIT (KEYS_PER_SPLIT / 32)
// scale * log2(e): scores computed in log2 domain for raw ex2
#define QSCALE_LOG2E 0.2550347222435f

// Scratch (device globals — no allocation)
__device__ float g_qkv[384 * 4096];        // q,k rows: [o][n], o = h*96 + r
__device__ float g_vT[4 * 4096 * 32];      // v: [h][n][d]
// split-K partials: o [split][h][row][state][d], l [split][h][row][state]
__device__ float g_po[NSPLIT * 4 * 4096 * 2 * 32];
__device__ float g_pl[NSPLIT * 4 * 4096 * 2];

// ---------------------------------------------------------------------------
__device__ __forceinline__ float ex2f(float x) {
    float y;
    asm("ex2.approx.ftz.f32 %0, %1;" : "=f"(y) : "f"(x));
    return y;
}
// pack {lo, hi} -> f16x2
__device__ __forceinline__ uint32_t pack_f16x2(float lo, float hi) {
    uint32_t r;
    asm("cvt.rn.f16x2.f32 %0, %1, %2;" : "=r"(r) : "f"(hi), "f"(lo));
    return r;
}
// D += A * B  (m16n8k16, f16 in, fp32 accum)
__device__ __forceinline__ void mma_f16(float* d, const uint32_t* a, const uint32_t* b) {
    asm volatile(
        "mma.sync.aligned.m16n8k16.row.col.f32.f16.f16.f32 "
        "{%0,%1,%2,%3}, {%4,%5,%6,%7}, {%8,%9}, {%0,%1,%2,%3};"
        : "+f"(d[0]), "+f"(d[1]), "+f"(d[2]), "+f"(d[3])
        : "r"(a[0]), "r"(a[1]), "r"(a[2]), "r"(a[3]), "r"(b[0]), "r"(b[1]));
}

// ===========================================================================
// Kernel 1: QKV projection (R14 64x64 tile) + register prefetch of k-step 1.
// grid (64 n-tiles, 6 o-tiles) = 384 CTAs, 256 threads.
// ===========================================================================
__global__ __launch_bounds__(256) void qkv_proj_kernel(const float* __restrict__ x,
                                                       const float* __restrict__ w) {
    __shared__ float sW[64 * 64];   // [o_local][k_local]
    __shared__ float sX[64 * 64];   // [c_local][n_local]
    const int tid = threadIdx.x;
    const int n0 = blockIdx.x * 64;
    const int o0 = blockIdx.y * 64;
    const int tx = tid & 15;        // n group (4 cols)
    const int ty = tid >> 4;        // o group (4 rows)

    float acc[4][4] = {};

    // ---- fill k-step 0 directly; prefetch k-step 1 into registers ----
    #pragma unroll
    for (int t = 0; t < 4; t++) {
        int i = tid + t * 256;
        int r = i >> 4, q4 = i & 15;
        *(float4*)&sW[r * 64 + q4 * 4] = *(const float4*)&w[(o0 + r) * 128 + q4 * 4];
    }
    #pragma unroll
    for (int t = 0; t < 16; t++) {
        int i = tid + t * 256;
        int cl = i >> 6, j = i & 63;
        int n = n0 + j;
        int hh = n >> 8, ww = (n >> 4) & 15, zz = n & 15;
        sX[cl * 64 + j] = x[cl * 32768 + hh * 2048 + ww * 64 + zz * 2];
    }
    float4 wr[4];
    float  xr[16];
    #pragma unroll
    for (int t = 0; t < 4; t++) {
        int i = tid + t * 256;
        int r = i >> 4, q4 = i & 15;
        wr[t] = *(const float4*)&w[(o0 + r) * 128 + 64 + q4 * 4];
    }
    #pragma unroll
    for (int t = 0; t < 16; t++) {
        int i = tid + t * 256;
        int cl = i >> 6, j = i & 63;
        int n = n0 + j;
        int hh = n >> 8, ww = (n >> 4) & 15, zz = n & 15;
        xr[t] = x[(64 + cl) * 32768 + hh * 2048 + ww * 64 + zz * 2];
    }

    #pragma unroll
    for (int ks = 0; ks < 2; ks++) {
        __syncthreads();
        if (ks == 1) {   // store prefetched k-step 1
            #pragma unroll
            for (int t = 0; t < 4; t++) {
                int i = tid + t * 256;
                int r = i >> 4, q4 = i & 15;
                *(float4*)&sW[r * 64 + q4 * 4] = wr[t];
            }
            #pragma unroll
            for (int t = 0; t < 16; t++) {
                int i = tid + t * 256;
                int cl = i >> 6, j = i & 63;
                sX[cl * 64 + j] = xr[t];
            }
            __syncthreads();
        }

        #pragma unroll
        for (int k = 0; k < 64; k += 4) {
            float xk[4][4];
            #pragma unroll
            for (int kk = 0; kk < 4; kk++) {
                float4 xv = *(float4*)&sX[(k + kk) * 64 + 4 * tx];
                xk[kk][0] = xv.x; xk[kk][1] = xv.y; xk[kk][2] = xv.z; xk[kk][3] = xv.w;
            }
            #pragma unroll
            for (int i = 0; i < 4; i++) {
                float4 wv = *(float4*)&sW[(4 * ty + i) * 64 + k];
                float wk[4] = {wv.x, wv.y, wv.z, wv.w};
                #pragma unroll
                for (int kk = 0; kk < 4; kk++)
                    #pragma unroll
                    for (int j = 0; j < 4; j++)
                        acc[i][j] += wk[kk] * xk[kk][j];
            }
        }
        if (ks == 0) __syncthreads();   // keep store of ks=1 off live sX reads
    }

    #pragma unroll
    for (int i = 0; i < 4; i++) {
        int o = o0 + 4 * ty + i;
        int r = o % 96;
        if (r < 64) {
            *(float4*)&g_qkv[o * 4096 + n0 + 4 * tx] =
                make_float4(acc[i][0], acc[i][1], acc[i][2], acc[i][3]);
        } else {
            int h = o / 96, d = r - 64;
            int nb = n0 + 4 * tx;
            #pragma unroll
            for (int j = 0; j < 4; j++)
                g_vT[(h * 4096 + nb + j) * 32 + d] = acc[i][j];
        }
    }
}

// ===========================================================================
// Kernel 2: dual-softmax attention, ALL-f16 MMA (QK and PV), register P.
// grid (64 row-tiles, 4 heads, 2 splits) = 512 CTAs, 128 threads (4 warps).
// K stored as f16x2 [dimpair][key] (mirror of proven V layout).
// Double-buffered smem, one __syncthreads per 32-key tile.
// ===========================================================================
__global__ __launch_bounds__(128, 4) void diff_attn_mma(void) {
    __shared__ __align__(16) uint32_t sKh[2][16 * 40];  // K f16x2 [dimpair][key], pad 40
    __shared__ __align__(16) uint32_t sVh[2][16 * 40];  // V f16x2 [keypair][dim], pad 40

    const int tid  = threadIdx.x;
    const int lane = tid & 31;
    const int warp = tid >> 5;
    const int h    = blockIdx.y;
    const int i0   = blockIdx.x * 64;
    const int spl  = blockIdx.z;
    const int kbase = spl * KEYS_PER_SPLIT;

    const float* qb = g_qkv + (h * 96) * 4096;
    const float* kb = qb + 32 * 4096;
    const float* vb = g_vT + h * 4096 * 32;

    const int qr = lane >> 2;   // 0..7
    const int qc = lane & 3;    // 0..3

    // ---- persistent Q fragments, f16x2 (scale*log2e folded): [hf][4] ----
    uint32_t qa[2][4];
    {
        const int r = i0 + warp * 16 + qr;
        #pragma unroll
        for (int hf = 0; hf < 2; hf++) {
            const int d0 = hf * 16 + 2 * qc;
            qa[hf][0] = pack_f16x2(qb[d0 * 4096 + r] * QSCALE_LOG2E,
                                   qb[(d0 + 1) * 4096 + r] * QSCALE_LOG2E);
            qa[hf][1] = pack_f16x2(qb[d0 * 4096 + r + 8] * QSCALE_LOG2E,
                                   qb[(d0 + 1) * 4096 + r + 8] * QSCALE_LOG2E);
            qa[hf][2] = pack_f16x2(qb[(d0 + 8) * 4096 + r] * QSCALE_LOG2E,
                                   qb[(d0 + 9) * 4096 + r] * QSCALE_LOG2E);
            qa[hf][3] = pack_f16x2(qb[(d0 + 8) * 4096 + r + 8] * QSCALE_LOG2E,
                                   qb[(d0 + 9) * 4096 + r + 8] * QSCALE_LOG2E);
        }
    }

    float of[2][4][4] = {};    // [state][nc(dim 8-chunk)][frag]
    float lacc[2][2] = {};     // [state][lo/hi row]

    // fill mapping: 128 threads; K dimpair pd x 4 keys ; V keypair pd x 4 dims
    const int pd = tid >> 3;          // 0..15
    const int pc = (tid & 7) * 4;     // 0..28

    float4 kfA, kfB, vfA, vfB;
    // prologue: tile 0 -> stage 0 ; tile 1 -> regs
    kfA = *(const float4*)&kb[(2 * pd) * 4096 + kbase + pc];
    kfB = *(const float4*)&kb[(2 * pd + 1) * 4096 + kbase + pc];
    vfA = *(const float4*)&vb[(kbase + 2 * pd) * 32 + pc];
    vfB = *(const float4*)&vb[(kbase + 2 * pd + 1) * 32 + pc];
    {
        uint4 kp, vp;
        kp.x = pack_f16x2(kfA.x, kfB.x);
        kp.y = pack_f16x2(kfA.y, kfB.y);
        kp.z = pack_f16x2(kfA.z, kfB.z);
        kp.w = pack_f16x2(kfA.w, kfB.w);
        *(uint4*)&sKh[0][pd * 40 + pc] = kp;
        vp.x = pack_f16x2(vfA.x, vfB.x);
        vp.y = pack_f16x2(vfA.y, vfB.y);
        vp.z = pack_f16x2(vfA.z, vfB.z);
        vp.w = pack_f16x2(vfA.w, vfB.w);
        *(uint4*)&sVh[0][pd * 40 + pc] = vp;
    }
    {
        const int j0 = kbase + 32;
        kfA = *(const float4*)&kb[(2 * pd) * 4096 + j0 + pc];
        kfB = *(const float4*)&kb[(2 * pd + 1) * 4096 + j0 + pc];
        vfA = *(const float4*)&vb[(j0 + 2 * pd) * 32 + pc];
        vfB = *(const float4*)&vb[(j0 + 2 * pd + 1) * 32 + pc];
    }
    __syncthreads();

    for (int jt = 0; jt < TILES_PER_SPLIT; jt++) {
        const int cur = jt & 1;
        const int nxt = cur ^ 1;

        // store tile jt+1 (in regs) into the other stage; prefetch jt+2
        if (jt + 1 < TILES_PER_SPLIT) {
            uint4 kp, vp;
            kp.x = pack_f16x2(kfA.x, kfB.x);
            kp.y = pack_f16x2(kfA.y, kfB.y);
            kp.z = pack_f16x2(kfA.z, kfB.z);
            kp.w = pack_f16x2(kfA.w, kfB.w);
            *(uint4*)&sKh[nxt][pd * 40 + pc] = kp;
            vp.x = pack_f16x2(vfA.x, vfB.x);
            vp.y = pack_f16x2(vfA.y, vfB.y);
            vp.z = pack_f16x2(vfA.z, vfB.z);
            vp.w = pack_f16x2(vfA.w, vfB.w);
            *(uint4*)&sVh[nxt][pd * 40 + pc] = vp;
        }
        if (jt + 2 < TILES_PER_SPLIT) {
            const int j0 = kbase + (jt + 2) * 32;
            kfA = *(const float4*)&kb[(2 * pd) * 4096 + j0 + pc];
            kfB = *(const float4*)&kb[(2 * pd + 1) * 4096 + j0 + pc];
            vfA = *(const float4*)&vb[(j0 + 2 * pd) * 32 + pc];
            vfB = *(const float4*)&vb[(j0 + 2 * pd + 1) * 32 + pc];
        }

        // ---- MMA1 (f16 k16) + exp + in-register f16 A-frag pack ----
        const uint32_t* cK = sKh[cur];
        const uint32_t* cV = sVh[cur];
        uint32_t pa[2][2][4];   // [state][k16-chunk][a-frag]
        #pragma unroll
        for (int hf = 0; hf < 2; hf++) {
            float sf[4][4] = {};
            #pragma unroll
            for (int nc = 0; nc < 4; nc++) {
                uint32_t b[2];
                b[0] = cK[(hf * 8 + qc) * 40 + nc * 8 + qr];
                b[1] = cK[(hf * 8 + qc + 4) * 40 + nc * 8 + qr];
                mma_f16(sf[nc], qa[hf], b);
            }
            float ll = 0.f, lh = 0.f;
            #pragma unroll
            for (int nc = 0; nc < 4; nc++) {
                float e0 = ex2f(sf[nc][0]);
                float e1 = ex2f(sf[nc][1]);
                float e2 = ex2f(sf[nc][2]);
                float e3 = ex2f(sf[nc][3]);
                ll += e0 + e1;
                lh += e2 + e3;
                const int ch = nc >> 1;
                const int aoff = (nc & 1) * 2;
                pa[hf][ch][aoff + 0] = pack_f16x2(e0, e1);
                pa[hf][ch][aoff + 1] = pack_f16x2(e2, e3);
            }
            lacc[hf][0] += ll;
            lacc[hf][1] += lh;
        }

        // ---- PV (f16 m16n8k16): O_s += P_s x V, V fragments shared ----
        #pragma unroll
        for (int c = 0; c < 2; c++) {
            #pragma unroll
            for (int nc = 0; nc < 4; nc++) {
                uint32_t b[2];
                b[0] = cV[(c * 8 + qc) * 40 + nc * 8 + qr];
                b[1] = cV[(c * 8 + qc + 4) * 40 + nc * 8 + qr];
                mma_f16(of[0][nc], pa[0][c], b);
                mma_f16(of[1][nc], pa[1][c], b);
            }
        }

        __syncthreads();   // single barrier per tile
    }

    // ---- epilogue: quad-reduce l, write RAW partials ----
    #pragma unroll
    for (int s = 1; s < 4; s <<= 1) {
        #pragma unroll
        for (int hf = 0; hf < 2; hf++) {
            lacc[hf][0] += __shfl_xor_sync(0xffffffffu, lacc[hf][0], s);
            lacc[hf][1] += __shfl_xor_sync(0xffffffffu, lacc[hf][1], s);
        }
    }

    const int row_lo = i0 + warp * 16 + qr;
    const int b_lo = ((spl * 4 + h) * 4096 + row_lo) * 2;
    const int b_hi = b_lo + 16;   // row_lo + 8
    #pragma unroll
    for (int st = 0; st < 2; st++) {
        #pragma unroll
        for (int nc = 0; nc < 4; nc++) {
            const int col = nc * 8 + qc * 2;
            *(float2*)&g_po[(b_lo + st) * 32 + col] =
                make_float2(of[st][nc][0], of[st][nc][1]);
            *(float2*)&g_po[(b_hi + st) * 32 + col] =
                make_float2(of[st][nc][2], of[st][nc][3]);
        }
    }
    if (qc == 0) {
        #pragma unroll
        for (int st = 0; st < 2; st++) {
            g_pl[b_lo + st] = lacc[st][0];
            g_pl[b_hi + st] = lacc[st][1];
        }
    }
}

// ===========================================================================
// Kernel 3: split-K reduce + differential combine.
// ===========================================================================
__global__ __launch_bounds__(256) void diff_reduce(float* __restrict__ out) {
    const int idx = blockIdx.x * 256 + threadIdx.x;   // over 4*4096*32
    const int d   = idx & 31;
    const int hn  = idx >> 5;                          // h*4096 + n

    const int STRIDE_O = 4 * 4096 * 2 * 32;
    const int STRIDE_L = 4 * 4096 * 2;
    const int bo = hn * 2 * 32;
    const int bl = hn * 2;

    float o1 = g_po[bo + d]      + g_po[STRIDE_O + bo + d];
    float o2 = g_po[bo + 32 + d] + g_po[STRIDE_O + bo + 32 + d];
    float l1 = g_pl[bl]          + g_pl[STRIDE_L + bl];
    float l2 = g_pl[bl + 1]      + g_pl[STRIDE_L + bl + 1];

    out[idx] = o1 / l1 - LAMBDA_F * (o2 / l2);
}

// ===========================================================================
extern "C" void kernel_launch(void* const* d_in, const int* in_sizes, int n_in,
                              void* d_out, int out_size) {
    const float* x = (const float*)d_in[0];       // (1,128,32,32,32)
    const float* w = (const float*)d_in[1];       // (384,128)
    float* out = (float*)d_out;                   // (1,128,16,16,16) fp32

    qkv_proj_kernel<<<dim3(64, 6), 256>>>(x, w);
    diff_attn_mma<<<dim3(64, 4, NSPLIT), 128>>>();
    diff_reduce<<<(4 * 4096 * 32) / 256, 256>>>(out);
}

// round 17
// speedup vs baseline: 1.3500x; 1.0909x over previous
#include <cuda_runtime.h>
#include <cstdint>
#include <math.h>

// Problem constants
//   x: (1,128,32,32,32) fp32 ; w_qkv: (384,128) fp32
//   subsample ::2 -> N = 4096 tokens, HEADS=4, head_dim=32, d_half=16
//   scale=1/sqrt(32), LAMBDA=0.1
//   out flat index = h*131072 + n*32 + d  (validated R4/R5)

#define N_TOK    4096
#define LAMBDA_F 0.1f
#define NSPLIT   2
#define KEYS_PER_SPLIT (N_TOK / NSPLIT)
#define TILES_PER_SPLIT (KEYS_PER_SPLIT / 32)
// scale * log2(e): scores computed in log2 domain for raw ex2
#define QSCALE_LOG2E 0.2550347222435f

// Scratch (device globals — no allocation)
__device__ float    g_qkv[384 * 4096];        // q rows used: [h*96 + d][n], d<32
__device__ uint32_t g_kh[4 * 16 * 4096];      // K f16x2: [h][dimpair][n] = {k[2dp][n], k[2dp+1][n]}
__device__ uint32_t g_vh[4 * 2048 * 32];      // V f16x2: [h][keypair][d] = {v[2kp][d], v[2kp+1][d]}
// split-K partials: o [split][h][row][state][d], l [split][h][row][state]
__device__ float g_po[NSPLIT * 4 * 4096 * 2 * 32];
__device__ float g_pl[NSPLIT * 4 * 4096 * 2];

// ---------------------------------------------------------------------------
__device__ __forceinline__ float ex2f(float x) {
    float y;
    asm("ex2.approx.ftz.f32 %0, %1;" : "=f"(y) : "f"(x));
    return y;
}
// pack {lo, hi} -> f16x2
__device__ __forceinline__ uint32_t pack_f16x2(float lo, float hi) {
    uint32_t r;
    asm("cvt.rn.f16x2.f32 %0, %1, %2;" : "=r"(r) : "f"(hi), "f"(lo));
    return r;
}
// D += A * B  (m16n8k16, f16 in, fp32 accum)
__device__ __forceinline__ void mma_f16(float* d, const uint32_t* a, const uint32_t* b) {
    asm volatile(
        "mma.sync.aligned.m16n8k16.row.col.f32.f16.f16.f32 "
        "{%0,%1,%2,%3}, {%4,%5,%6,%7}, {%8,%9}, {%0,%1,%2,%3};"
        : "+f"(d[0]), "+f"(d[1]), "+f"(d[2]), "+f"(d[3])
        : "r"(a[0]), "r"(a[1]), "r"(a[2]), "r"(a[3]), "r"(b[0]), "r"(b[1]));
}

// ===========================================================================
// Kernel 1: QKV projection; writes q fp32, K/V directly in f16x2
// attention-native layouts. grid (64 n-tiles, 6 o-tiles), 256 threads.
// Each thread's 4 output rows are 4-aligned -> never straddle q/k/v segments.
// ===========================================================================
__global__ __launch_bounds__(256) void qkv_proj_kernel(const float* __restrict__ x,
                                                       const float* __restrict__ w) {
    __shared__ float sW[64 * 64];   // [o_local][k_local]
    __shared__ float sX[64 * 64];   // [c_local][n_local]
    const int tid = threadIdx.x;
    const int n0 = blockIdx.x * 64;
    const int o0 = blockIdx.y * 64;
    const int tx = tid & 15;        // n group (4 cols)
    const int ty = tid >> 4;        // o group (4 rows)

    float acc[4][4] = {};

    // ---- fill k-step 0 directly; prefetch k-step 1 into registers ----
    #pragma unroll
    for (int t = 0; t < 4; t++) {
        int i = tid + t * 256;
        int r = i >> 4, q4 = i & 15;
        *(float4*)&sW[r * 64 + q4 * 4] = *(const float4*)&w[(o0 + r) * 128 + q4 * 4];
    }
    #pragma unroll
    for (int t = 0; t < 16; t++) {
        int i = tid + t * 256;
        int cl = i >> 6, j = i & 63;
        int n = n0 + j;
        int hh = n >> 8, ww = (n >> 4) & 15, zz = n & 15;
        sX[cl * 64 + j] = x[cl * 32768 + hh * 2048 + ww * 64 + zz * 2];
    }
    float4 wr[4];
    float  xr[16];
    #pragma unroll
    for (int t = 0; t < 4; t++) {
        int i = tid + t * 256;
        int r = i >> 4, q4 = i & 15;
        wr[t] = *(const float4*)&w[(o0 + r) * 128 + 64 + q4 * 4];
    }
    #pragma unroll
    for (int t = 0; t < 16; t++) {
        int i = tid + t * 256;
        int cl = i >> 6, j = i & 63;
        int n = n0 + j;
        int hh = n >> 8, ww = (n >> 4) & 15, zz = n & 15;
        xr[t] = x[(64 + cl) * 32768 + hh * 2048 + ww * 64 + zz * 2];
    }

    #pragma unroll
    for (int ks = 0; ks < 2; ks++) {
        __syncthreads();
        if (ks == 1) {   // store prefetched k-step 1
            #pragma unroll
            for (int t = 0; t < 4; t++) {
                int i = tid + t * 256;
                int r = i >> 4, q4 = i & 15;
                *(float4*)&sW[r * 64 + q4 * 4] = wr[t];
            }
            #pragma unroll
            for (int t = 0; t < 16; t++) {
                int i = tid + t * 256;
                int cl = i >> 6, j = i & 63;
                sX[cl * 64 + j] = xr[t];
            }
            __syncthreads();
        }

        #pragma unroll
        for (int k = 0; k < 64; k += 4) {
            float xk[4][4];
            #pragma unroll
            for (int kk = 0; kk < 4; kk++) {
                float4 xv = *(float4*)&sX[(k + kk) * 64 + 4 * tx];
                xk[kk][0] = xv.x; xk[kk][1] = xv.y; xk[kk][2] = xv.z; xk[kk][3] = xv.w;
            }
            #pragma unroll
            for (int i = 0; i < 4; i++) {
                float4 wv = *(float4*)&sW[(4 * ty + i) * 64 + k];
                float wk[4] = {wv.x, wv.y, wv.z, wv.w};
                #pragma unroll
                for (int kk = 0; kk < 4; kk++)
                    #pragma unroll
                    for (int j = 0; j < 4; j++)
                        acc[i][j] += wk[kk] * xk[kk][j];
            }
        }
        if (ks == 0) __syncthreads();
    }

    // ---- epilogue: q -> fp32 ; k -> f16x2 dim-pairs ; v -> f16x2 key-pairs ----
    const int o0r = o0 + 4 * ty;     // first of this thread's 4 rows
    const int h   = o0r / 96;
    const int r   = o0r % 96;
    const int nb  = n0 + 4 * tx;

    if (r < 32) {                    // q rows
        #pragma unroll
        for (int i = 0; i < 4; i++)
            *(float4*)&g_qkv[(o0r + i) * 4096 + nb] =
                make_float4(acc[i][0], acc[i][1], acc[i][2], acc[i][3]);
    } else if (r < 64) {             // k rows: pack dims (2dp, 2dp+1)
        const int dp = (r - 32) >> 1;
        uint4 p0, p1;
        p0.x = pack_f16x2(acc[0][0], acc[1][0]);
        p0.y = pack_f16x2(acc[0][1], acc[1][1]);
        p0.z = pack_f16x2(acc[0][2], acc[1][2]);
        p0.w = pack_f16x2(acc[0][3], acc[1][3]);
        p1.x = pack_f16x2(acc[2][0], acc[3][0]);
        p1.y = pack_f16x2(acc[2][1], acc[3][1]);
        p1.z = pack_f16x2(acc[2][2], acc[3][2]);
        p1.w = pack_f16x2(acc[2][3], acc[3][3]);
        *(uint4*)&g_kh[(h * 16 + dp) * 4096 + nb]     = p0;
        *(uint4*)&g_kh[(h * 16 + dp + 1) * 4096 + nb] = p1;
    } else {                         // v rows: pack keys (2kp, 2kp+1)
        const int d  = r - 64;
        const int kp = nb >> 1;
        #pragma unroll
        for (int i = 0; i < 4; i++) {
            g_vh[(h * 2048 + kp) * 32 + d + i]     = pack_f16x2(acc[i][0], acc[i][1]);
            g_vh[(h * 2048 + kp + 1) * 32 + d + i] = pack_f16x2(acc[i][2], acc[i][3]);
        }
    }
}

// ===========================================================================
// Kernel 2: dual-softmax attention, all-f16 MMA, pre-packed K/V.
// grid (64 row-tiles, 4 heads, 2 splits) = 512 CTAs, 128 threads (4 warps).
// Fill = 2 LDG.128 + 2 STS.128 per thread per tile (no conversion).
// ===========================================================================
__global__ __launch_bounds__(128, 4) void diff_attn_mma(void) {
    __shared__ __align__(16) uint32_t sKh[2][16 * 40];  // K f16x2 [dimpair][key], pad 40
    __shared__ __align__(16) uint32_t sVh[2][16 * 40];  // V f16x2 [keypair][dim], pad 40

    const int tid  = threadIdx.x;
    const int lane = tid & 31;
    const int warp = tid >> 5;
    const int h    = blockIdx.y;
    const int i0   = blockIdx.x * 64;
    const int spl  = blockIdx.z;
    const int kbase = spl * KEYS_PER_SPLIT;

    const float*    qb  = g_qkv + (h * 96) * 4096;
    const uint32_t* khp = g_kh + h * 16 * 4096;
    const uint32_t* vhp = g_vh + h * 2048 * 32;

    const int qr = lane >> 2;   // 0..7
    const int qc = lane & 3;    // 0..3

    // ---- persistent Q fragments, f16x2 (scale*log2e folded): [hf][4] ----
    uint32_t qa[2][4];
    {
        const int r = i0 + warp * 16 + qr;
        #pragma unroll
        for (int hf = 0; hf < 2; hf++) {
            const int d0 = hf * 16 + 2 * qc;
            qa[hf][0] = pack_f16x2(qb[d0 * 4096 + r] * QSCALE_LOG2E,
                                   qb[(d0 + 1) * 4096 + r] * QSCALE_LOG2E);
            qa[hf][1] = pack_f16x2(qb[d0 * 4096 + r + 8] * QSCALE_LOG2E,
                                   qb[(d0 + 1) * 4096 + r + 8] * QSCALE_LOG2E);
            qa[hf][2] = pack_f16x2(qb[(d0 + 8) * 4096 + r] * QSCALE_LOG2E,
                                   qb[(d0 + 9) * 4096 + r] * QSCALE_LOG2E);
            qa[hf][3] = pack_f16x2(qb[(d0 + 8) * 4096 + r + 8] * QSCALE_LOG2E,
                                   qb[(d0 + 9) * 4096 + r + 8] * QSCALE_LOG2E);
        }
    }

    float of[2][4][4] = {};    // [state][nc(dim 8-chunk)][frag]
    float lacc[2][2] = {};     // [state][lo/hi row]

    // fill mapping: K row pd (dimpair) x keys pc..pc+3 ; V row pd (keypair) x dims
    const int pd = tid >> 3;          // 0..15
    const int pc = (tid & 7) * 4;     // 0..28

    uint4 kq, vq;
    // prologue: tile 0 -> stage 0 ; tile 1 -> regs
    kq = *(const uint4*)&khp[pd * 4096 + kbase + pc];
    vq = *(const uint4*)&vhp[((kbase >> 1) + pd) * 32 + pc];
    *(uint4*)&sKh[0][pd * 40 + pc] = kq;
    *(uint4*)&sVh[0][pd * 40 + pc] = vq;
    {
        const int j0 = kbase + 32;
        kq = *(const uint4*)&khp[pd * 4096 + j0 + pc];
        vq = *(const uint4*)&vhp[((j0 >> 1) + pd) * 32 + pc];
    }
    __syncthreads();

    for (int jt = 0; jt < TILES_PER_SPLIT; jt++) {
        const int cur = jt & 1;
        const int nxt = cur ^ 1;

        // store tile jt+1 (in regs) into the other stage; prefetch jt+2
        if (jt + 1 < TILES_PER_SPLIT) {
            *(uint4*)&sKh[nxt][pd * 40 + pc] = kq;
            *(uint4*)&sVh[nxt][pd * 40 + pc] = vq;
        }
        if (jt + 2 < TILES_PER_SPLIT) {
            const int j0 = kbase + (jt + 2) * 32;
            kq = *(const uint4*)&khp[pd * 4096 + j0 + pc];
            vq = *(const uint4*)&vhp[((j0 >> 1) + pd) * 32 + pc];
        }

        // ---- MMA1 (f16 k16) + exp + in-register f16 A-frag pack ----
        const uint32_t* cK = sKh[cur];
        const uint32_t* cV = sVh[cur];
        uint32_t pa[2][2][4];   // [state][k16-chunk][a-frag]
        #pragma unroll
        for (int hf = 0; hf < 2; hf++) {
            float sf[4][4] = {};
            #pragma unroll
            for (int nc = 0; nc < 4; nc++) {
                uint32_t b[2];
                b[0] = cK[(hf * 8 + qc) * 40 + nc * 8 + qr];
                b[1] = cK[(hf * 8 + qc + 4) * 40 + nc * 8 + qr];
                mma_f16(sf[nc], qa[hf], b);
            }
            float ll = 0.f, lh = 0.f;
            #pragma unroll
            for (int nc = 0; nc < 4; nc++) {
                float e0 = ex2f(sf[nc][0]);
                float e1 = ex2f(sf[nc][1]);
                float e2 = ex2f(sf[nc][2]);
                float e3 = ex2f(sf[nc][3]);
                ll += e0 + e1;
                lh += e2 + e3;
                const int ch = nc >> 1;
                const int aoff = (nc & 1) * 2;
                pa[hf][ch][aoff + 0] = pack_f16x2(e0, e1);
                pa[hf][ch][aoff + 1] = pack_f16x2(e2, e3);
            }
            lacc[hf][0] += ll;
            lacc[hf][1] += lh;
        }

        // ---- PV (f16 m16n8k16): O_s += P_s x V, V fragments shared ----
        #pragma unroll
        for (int c = 0; c < 2; c++) {
            #pragma unroll
            for (int nc = 0; nc < 4; nc++) {
                uint32_t b[2];
                b[0] = cV[(c * 8 + qc) * 40 + nc * 8 + qr];
                b[1] = cV[(c * 8 + qc + 4) * 40 + nc * 8 + qr];
                mma_f16(of[0][nc], pa[0][c], b);
                mma_f16(of[1][nc], pa[1][c], b);
            }
        }

        __syncthreads();   // single barrier per tile
    }

    // ---- epilogue: quad-reduce l, write RAW partials ----
    #pragma unroll
    for (int s = 1; s < 4; s <<= 1) {
        #pragma unroll
        for (int hf = 0; hf < 2; hf++) {
            lacc[hf][0] += __shfl_xor_sync(0xffffffffu, lacc[hf][0], s);
            lacc[hf][1] += __shfl_xor_sync(0xffffffffu, lacc[hf][1], s);
        }
    }

    const int row_lo = i0 + warp * 16 + qr;
    const int b_lo = ((spl * 4 + h) * 4096 + row_lo) * 2;
    const int b_hi = b_lo + 16;   // row_lo + 8
    #pragma unroll
    for (int st = 0; st < 2; st++) {
        #pragma unroll
        for (int nc = 0; nc < 4; nc++) {
            const int col = nc * 8 + qc * 2;
            *(float2*)&g_po[(b_lo + st) * 32 + col] =
                make_float2(of[st][nc][0], of[st][nc][1]);
            *(float2*)&g_po[(b_hi + st) * 32 + col] =
                make_float2(of[st][nc][2], of[st][nc][3]);
        }
    }
    if (qc == 0) {
        #pragma unroll
        for (int st = 0; st < 2; st++) {
            g_pl[b_lo + st] = lacc[st][0];
            g_pl[b_hi + st] = lacc[st][1];
        }
    }
}

// ===========================================================================
// Kernel 3: split-K reduce + differential combine.
// ===========================================================================
__global__ __launch_bounds__(256) void diff_reduce(float* __restrict__ out) {
    const int idx = blockIdx.x * 256 + threadIdx.x;   // over 4*4096*32
    const int d   = idx & 31;
    const int hn  = idx >> 5;                          // h*4096 + n

    const int STRIDE_O = 4 * 4096 * 2 * 32;
    const int STRIDE_L = 4 * 4096 * 2;
    const int bo = hn * 2 * 32;
    const int bl = hn * 2;

    float o1 = g_po[bo + d]      + g_po[STRIDE_O + bo + d];
    float o2 = g_po[bo + 32 + d] + g_po[STRIDE_O + bo + 32 + d];
    float l1 = g_pl[bl]          + g_pl[STRIDE_L + bl];
    float l2 = g_pl[bl + 1]      + g_pl[STRIDE_L + bl + 1];

    out[idx] = o1 / l1 - LAMBDA_F * (o2 / l2);
}

// ===========================================================================
extern "C" void kernel_launch(void* const* d_in, const int* in_sizes, int n_in,
                              void* d_out, int out_size) {
    const float* x = (const float*)d_in[0];       // (1,128,32,32,32)
    const float* w = (const float*)d_in[1];       // (384,128)
    float* out = (float*)d_out;                   // (1,128,16,16,16) fp32

    qkv_proj_kernel<<<dim3(64, 6), 256>>>(x, w);
    diff_attn_mma<<<dim3(64, 4, NSPLIT), 128>>>();
    diff_reduce<<<(4 * 4096 * 32) / 256, 256>>>(out);
}